// round 10
// baseline (speedup 1.0000x reference)
#include <cuda_runtime.h>

// Convex_f: out[b,j,k] = (interior && Dy>0) ? 0.5*(y[j-1]+y[j+1]) - param[j]
//                                          : y[j] - param[j]   // bit-exact vs reference ((x+p)-p)
// where y = x + param, Dy = 2*y[j] - y[j-1] - y[j+1].
// Shapes: B=256, N=8192, K=16, float32, contiguous (B,N,K).
//
// R9: smem y-tile (as R8) but y is NOT carried in registers across the
// barrier — compute phase reads y0 from smem (conflict-free LDS.128).
// Persistent reg state drops to pr[4]; __launch_bounds__(256,6) -> 6 blocks/SM
// (75% occ cap) for better cross-block load/compute overlap.

constexpr int Bn = 256;
constexpr int Nn = 8192;
constexpr int Kn = 16;
constexpr int KV = Kn / 4;            // float4 per (b,j) row = 4
constexpr int TJ = 256;               // j-rows per block tile
constexpr int TILES_PER_B = Nn / TJ;  // 32
constexpr int CB = 256;               // threads per block
constexpr int EPT = (TJ * KV) / CB;   // float4 elements per thread = 4

__global__ __launch_bounds__(CB, 6)
void convex_kernel(const float4* __restrict__ x4,
                   const float4* __restrict__ p4,
                   float4* __restrict__ o4)
{
    // y tile with one halo row on each side: rows [-1 .. TJ], row jl at (jl+1)
    __shared__ float4 ys[(TJ + 2) * KV];

    int tile = blockIdx.x;
    int b    = tile >> 5;                  // tile / TILES_PER_B
    int jt   = (tile & (TILES_PER_B - 1)) * TJ;
    int base = b * (Nn * KV) + jt * KV;    // float4 offset of (b, jt, k=0)
    int tid  = threadIdx.x;

    // ---- Load phase: 8 coalesced LDG.128 per thread (front-batched) ----
    float4 pr[EPT];
    #pragma unroll
    for (int r = 0; r < EPT; r++) {
        int flat = r * CB + tid;           // = j_local*KV + kv
        float4 xv = x4[base + flat];
        float4 pv = p4[base + flat];
        pr[r] = pv;
        ys[flat + KV] = make_float4(xv.x + pv.x, xv.y + pv.y,
                                    xv.z + pv.z, xv.w + pv.w);
    }

    // Halo rows: j_local = -1 and j_local = TJ (clamped at global edges;
    // clamped values are never consumed because those j are non-interior).
    if (tid < 2 * KV) {
        int kvh = tid & (KV - 1);
        bool hi = tid >= KV;
        int jg  = hi ? (jt + TJ) : (jt - 1);
        jg = (jg < 0) ? 0 : ((jg > Nn - 1) ? (Nn - 1) : jg);
        int offh = b * (Nn * KV) + jg * KV + kvh;
        float4 xv = x4[offh];
        float4 pv = p4[offh];
        int slot = hi ? ((TJ + 1) * KV + kvh) : kvh;
        ys[slot] = make_float4(xv.x + pv.x, xv.y + pv.y, xv.z + pv.z, xv.w + pv.w);
    }

    __syncthreads();

    // ---- Compute phase: y0 and neighbors from smem, write out ----
    #pragma unroll
    for (int r = 0; r < EPT; r++) {
        int flat = r * CB + tid;
        int j    = jt + (flat >> 2);       // global j
        float4 ym = ys[flat];              // j-1
        float4 y0 = ys[flat + KV];         // j
        float4 yp = ys[flat + 2 * KV];     // j+1
        float4 p0 = pr[r];

        bool interior = (j > 0) && (j < Nn - 1);

        float4 out;
        {
            float s    = ym.x + yp.x;
            float Dy   = fmaf(2.0f, y0.x, -s);
            float alt  = fmaf(0.5f, s, -p0.x);
            float keep = y0.x - p0.x;
            out.x = (interior && Dy > 0.0f) ? alt : keep;
        }
        {
            float s    = ym.y + yp.y;
            float Dy   = fmaf(2.0f, y0.y, -s);
            float alt  = fmaf(0.5f, s, -p0.y);
            float keep = y0.y - p0.y;
            out.y = (interior && Dy > 0.0f) ? alt : keep;
        }
        {
            float s    = ym.z + yp.z;
            float Dy   = fmaf(2.0f, y0.z, -s);
            float alt  = fmaf(0.5f, s, -p0.z);
            float keep = y0.z - p0.z;
            out.z = (interior && Dy > 0.0f) ? alt : keep;
        }
        {
            float s    = ym.w + yp.w;
            float Dy   = fmaf(2.0f, y0.w, -s);
            float alt  = fmaf(0.5f, s, -p0.w);
            float keep = y0.w - p0.w;
            out.w = (interior && Dy > 0.0f) ? alt : keep;
        }

        o4[base + flat] = out;
    }
}

extern "C" void kernel_launch(void* const* d_in, const int* in_sizes, int n_in,
                              void* d_out, int out_size)
{
    const float4* x4 = (const float4*)d_in[0];
    const float4* p4 = (const float4*)d_in[1];
    float4* o4 = (float4*)d_out;

    int blocks = Bn * TILES_PER_B;        // 8192
    convex_kernel<<<blocks, CB>>>(x4, p4, o4);
}

// round 11
// speedup vs baseline: 1.0184x; 1.0184x over previous
#include <cuda_runtime.h>
#include <cstdint>

// Convex_f: out[b,j,k] = (interior && Dy>0) ? 0.5*(y[j-1]+y[j+1]) - param[j]
//                                          : y[j] - param[j]   // bit-exact vs reference ((x+p)-p)
// where y = x + param, Dy = 2*y[j] - y[j-1] - y[j+1].
// Shapes: B=256, N=8192, K=16, float32, contiguous (B,N,K).
//
// R11: cp.async tile load. Raw x and p tiles (+1-row halo each side) are
// copied global->smem with LDGSTS (no destination registers -> load depth
// is independent of reg budget). Compute phase forms y from smem on the fly.
// Occupancy smem-limited at ~33KB/block -> 6 blocks/SM, regs stay low.

constexpr int Bn = 256;
constexpr int Nn = 8192;
constexpr int Kn = 16;
constexpr int KV = Kn / 4;            // float4 per (b,j) row = 4
constexpr int TJ = 256;               // j-rows per block tile
constexpr int TILES_PER_B = Nn / TJ;  // 32
constexpr int CB = 256;               // threads per block
constexpr int EPT = (TJ * KV) / CB;   // float4 elements per thread = 4
constexpr int TROWS = (TJ + 2) * KV;  // tile rows incl. halo, in float4 units = 1032

__device__ __forceinline__ void cp_async16(uint32_t smem_addr, const void* gptr) {
    asm volatile("cp.async.cg.shared.global [%0], [%1], 16;\n"
                 :: "r"(smem_addr), "l"(gptr));
}
__device__ __forceinline__ void cp_async_commit_wait0() {
    asm volatile("cp.async.commit_group;\n");
    asm volatile("cp.async.wait_group 0;\n" ::: "memory");
}

__global__ __launch_bounds__(CB, 6)
void convex_kernel(const float4* __restrict__ x4,
                   const float4* __restrict__ p4,
                   float4* __restrict__ o4)
{
    // Raw tiles with one halo row each side: row jl stored at (jl+1)
    __shared__ float4 xs[TROWS];
    __shared__ float4 ps[TROWS];

    int tile = blockIdx.x;
    int b    = tile >> 5;                  // tile / TILES_PER_B
    int jt   = (tile & (TILES_PER_B - 1)) * TJ;
    int base = b * (Nn * KV) + jt * KV;    // float4 offset of (b, jt, k=0)
    int tid  = threadIdx.x;

    uint32_t xs_base = (uint32_t)__cvta_generic_to_shared(xs);
    uint32_t ps_base = (uint32_t)__cvta_generic_to_shared(ps);

    // ---- Async copy phase: 8 interior copies per thread, zero dest regs ----
    #pragma unroll
    for (int r = 0; r < EPT; r++) {
        int flat = r * CB + tid;           // = j_local*KV + kv
        cp_async16(xs_base + (flat + KV) * 16, &x4[base + flat]);
        cp_async16(ps_base + (flat + KV) * 16, &p4[base + flat]);
    }

    // Halo rows: j_local = -1 and j_local = TJ, both arrays (16 copies total).
    // Clamped at global edges; clamped values are never consumed (non-interior j).
    if (tid < 4 * KV) {
        int kvh  = tid & (KV - 1);
        int sel  = tid >> 2;               // 0: x lo, 1: x hi, 2: p lo, 3: p hi
        bool hi  = sel & 1;
        bool isp = sel >= 2;
        int jg   = hi ? (jt + TJ) : (jt - 1);
        jg = (jg < 0) ? 0 : ((jg > Nn - 1) ? (Nn - 1) : jg);
        int offh = b * (Nn * KV) + jg * KV + kvh;
        int slot = hi ? ((TJ + 1) * KV + kvh) : kvh;
        if (isp) cp_async16(ps_base + slot * 16, &p4[offh]);
        else     cp_async16(xs_base + slot * 16, &x4[offh]);
    }

    cp_async_commit_wait0();
    __syncthreads();

    // ---- Compute phase: form y from smem on the fly, write out ----
    #pragma unroll
    for (int r = 0; r < EPT; r++) {
        int flat = r * CB + tid;
        int j    = jt + (flat >> 2);       // global j

        float4 xmv = xs[flat];             float4 pmv = ps[flat];             // j-1
        float4 x0v = xs[flat + KV];        float4 p0  = ps[flat + KV];        // j
        float4 xpv = xs[flat + 2 * KV];    float4 ppv = ps[flat + 2 * KV];    // j+1

        bool interior = (j > 0) && (j < Nn - 1);

        float4 out;
        {
            float ym = xmv.x + pmv.x, y0 = x0v.x + p0.x, yp = xpv.x + ppv.x;
            float s    = ym + yp;
            float Dy   = fmaf(2.0f, y0, -s);
            float alt  = fmaf(0.5f, s, -p0.x);
            float keep = y0 - p0.x;
            out.x = (interior && Dy > 0.0f) ? alt : keep;
        }
        {
            float ym = xmv.y + pmv.y, y0 = x0v.y + p0.y, yp = xpv.y + ppv.y;
            float s    = ym + yp;
            float Dy   = fmaf(2.0f, y0, -s);
            float alt  = fmaf(0.5f, s, -p0.y);
            float keep = y0 - p0.y;
            out.y = (interior && Dy > 0.0f) ? alt : keep;
        }
        {
            float ym = xmv.z + pmv.z, y0 = x0v.z + p0.z, yp = xpv.z + ppv.z;
            float s    = ym + yp;
            float Dy   = fmaf(2.0f, y0, -s);
            float alt  = fmaf(0.5f, s, -p0.z);
            float keep = y0 - p0.z;
            out.z = (interior && Dy > 0.0f) ? alt : keep;
        }
        {
            float ym = xmv.w + pmv.w, y0 = x0v.w + p0.w, yp = xpv.w + ppv.w;
            float s    = ym + yp;
            float Dy   = fmaf(2.0f, y0, -s);
            float alt  = fmaf(0.5f, s, -p0.w);
            float keep = y0 - p0.w;
            out.w = (interior && Dy > 0.0f) ? alt : keep;
        }

        o4[base + flat] = out;
    }
}

extern "C" void kernel_launch(void* const* d_in, const int* in_sizes, int n_in,
                              void* d_out, int out_size)
{
    const float4* x4 = (const float4*)d_in[0];
    const float4* p4 = (const float4*)d_in[1];
    float4* o4 = (float4*)d_out;

    int blocks = Bn * TILES_PER_B;        // 8192
    convex_kernel<<<blocks, CB>>>(x4, p4, o4);
}